// round 8
// baseline (speedup 1.0000x reference)
#include <cuda_runtime.h>
#include <cuda_bf16.h>

// Shapes (fixed by dataset):
//   x:  (8, 64, 56, 56) fp32
//   lb: (64, 1, 1, 32)  fp32 (tiled linspace left edges, uniform bins)
//   rb: (64, 1, 1, 32)  fp32
//   out:(8, 32, 56, 56) fp32
#define NB   8
#define CI   64
#define CO   32
#define HW   3136                // 56*56
#define NPOS (NB * HW)           // 25088
#define PPB  32                  // positions per block (3136 % 32 == 0 -> 98/batch)
#define NG   8                   // channel groups per block
#define CPG  (CI / NG)           // 8 channels per group
#define NT   (PPB * NG)          // 256 threads
#define BPB  (HW / PPB)          // 98 blocks per batch

__global__ __launch_bounds__(NT)
void local_basis_kernel(const float* __restrict__ x,
                        const float* __restrict__ lb,
                        const float* __restrict__ rb,
                        float* __restrict__ out)
{
    // NG private accumulator copies; layout acc[g][k*PPB + pos].
    // Warp = one g with 32 consecutive pos -> bank = pos = lane for any k:
    // conflict-free RMW, init and reduction.
    __shared__ float acc[NG * CO * PPB];     // 8*32*32*4B = 32 KB

    const int tid = threadIdx.x;
    const int pos = tid & (PPB - 1);
    const int g   = tid >> 5;

    // Block never straddles a batch (98 blocks per batch).
    const int blk    = blockIdx.x;
    const int b      = blk / BPB;
    const int s_base = (blk - b * BPB) * PPB;
    const int s      = s_base + pos;

    // Bin geometry from the input arrays (uniform adjacent bins).
    const float lb0   = lb[0];
    const float w     = rb[0] - lb0;
    const float inv_w = 1.0f / w;
    const float c0    = -lb0 * inv_w;        // t = x*inv_w + c0 = (x-lb0)/w

    // Zero accumulators: 8192 floats / 256 thr = 8 float4 each.
    float4* accv = reinterpret_cast<float4*>(acc);
    #pragma unroll
    for (int i = 0; i < (NG * CO * PPB / 4) / NT; i++)
        accv[tid + i * NT] = make_float4(0.f, 0.f, 0.f, 0.f);
    __syncthreads();

    // Main loop. Each x lands in exactly one bin (adjacent bins of width
    // w < 1, so the reference's +-1 clip is inactive inside a bin, and every
    // non-containing bin yields an exact 0 through its relu). Branchless:
    // clamp the bin index; outside the domain one of the two max() guards
    // is exactly 0 -> exact-0 contribution, matching the reference.
    // Inside bin k: contribution = (norm*(x-lb_k)*(rb_k-x))^2
    //            = (4*tf*(1-tf))^2 with tf=(x-lb_k)/w, since norm*w^2 = 4.
    const float* xp = x + ((size_t)b * CI + (size_t)g * CPG) * HW + s;
    float* ag = acc + g * (CO * PPB) + pos;

    #pragma unroll
    for (int c = 0; c < CPG; c++) {
        const float xv = xp[c * HW];
        const float t  = fmaf(xv, inv_w, c0);
        float kf = floorf(t);
        kf = fmaxf(kf, 0.0f);
        kf = fminf(kf, (float)(CO - 1));
        const int   k  = (int)kf;
        const float tf = t - kf;
        const float g1 = fmaxf(tf, 0.0f);
        const float g2 = fmaxf(1.0f - tf, 0.0f);
        const float u  = g1 * g2 * 4.0f;     // == norm*(x-lb_k)*(rb_k-x)
        float* a = ag + k * PPB;
        *a = fmaf(u, u, *a);
    }
    __syncthreads();

    // Reduce NG copies + store: 1024 outputs / 256 thr = 4 each.
    // Lanes take consecutive o -> same k, consecutive pos: conflict-free
    // smem reads, 128B-coalesced global stores. No divisions (b, s_base
    // are block constants).
    #pragma unroll
    for (int i = 0; i < (CO * PPB) / NT; i++) {
        const int o  = tid + i * NT;         // 0..1023
        const int k  = o >> 5;               // o / PPB
        const int pp = o & (PPB - 1);        // o % PPB
        float sum = 0.0f;
        #pragma unroll
        for (int gg = 0; gg < NG; gg++)
            sum += acc[gg * (CO * PPB) + o];
        out[((size_t)b * CO + k) * HW + (s_base + pp)] = sum;
    }
}

extern "C" void kernel_launch(void* const* d_in, const int* in_sizes, int n_in,
                              void* d_out, int out_size)
{
    const float* x  = (const float*)d_in[0];
    const float* lb = (const float*)d_in[1];
    const float* rb = (const float*)d_in[2];
    float* out      = (float*)d_out;

    local_basis_kernel<<<NPOS / PPB, NT>>>(x, lb, rb, out);
}

// round 9
// speedup vs baseline: 1.0332x; 1.0332x over previous
#include <cuda_runtime.h>
#include <cuda_bf16.h>

// Shapes (fixed by dataset):
//   x:  (8, 64, 56, 56) fp32
//   lb: (64, 1, 1, 32)  fp32 (tiled uniform linspace left edges)
//   rb: (64, 1, 1, 32)  fp32
//   out:(8, 32, 56, 56) fp32
#define NB   8
#define CI   64
#define CO   32
#define HW   3136                 // 56*56
#define NPOS (NB * HW)            // 25088
#define PPB  64                   // positions per block
#define NG   8                    // channel groups = warps per block
#define CPG  (CI / NG)            // 8 channels per warp
#define NT   (NG * 32)            // 256 threads
#define BPB  (HW / PPB)           // 49 blocks per batch
#define ACCN (NG * CO * PPB)      // 16384 floats = 64 KB

__global__ __launch_bounds__(NT)
void local_basis_kernel(const float* __restrict__ x,
                        const float* __restrict__ lb,
                        const float* __restrict__ rb,
                        float* __restrict__ out)
{
    // One accumulator copy per warp (channel group): acc[g][k*PPB + pos].
    // Thread owns pos = lane and pos = lane+32:
    //   bank(g*2048 + k*64 + lane)      = lane
    //   bank(g*2048 + k*64 + 32 + lane) = lane
    // -> conflict-free RMW for both chains, any k.
    extern __shared__ float acc[];

    const int tid  = threadIdx.x;
    const int lane = tid & 31;
    const int g    = tid >> 5;

    const int blk    = blockIdx.x;
    const int b      = blk / BPB;            // block never straddles a batch
    const int s_base = (blk - b * BPB) * PPB;

    // Bin geometry from the input arrays (uniform adjacent bins).
    const float lb0   = lb[0];
    const float w     = rb[0] - lb0;
    const float inv_w = 1.0f / w;
    const float c0    = -lb0 * inv_w;        // t = x*inv_w + c0 = (x-lb0)/w

    // Zero accumulators: 16384 floats / 256 thr = 16 float4 each.
    float4* av = reinterpret_cast<float4*>(acc);
    #pragma unroll
    for (int i = 0; i < (ACCN / 4) / NT; i++)
        av[tid + i * NT] = make_float4(0.f, 0.f, 0.f, 0.f);
    __syncthreads();

    // Hoist ALL global loads first: MLP = 16, one DRAM exposure per warp.
    const float* xp = x + ((size_t)b * CI + (size_t)g * CPG) * HW + s_base + lane;
    float va[CPG], vb[CPG];
    #pragma unroll
    for (int c = 0; c < CPG; c++) {
        va[c] = xp[c * HW];          // position lane
        vb[c] = xp[c * HW + 32];     // position lane+32
    }

    float* aga = acc + g * (CO * PPB) + lane;   // pos = lane
    float* agb = aga + 32;                      // pos = lane + 32

    // Each x lands in exactly one bin (adjacent bins, width w < 1, so the
    // reference's +-1 clip is inactive inside a bin and every other bin is
    // an exact 0 through its relu). Inside bin k:
    //   contribution = (norm*(x-lb_k)*(rb_k-x))^2 = 16*(tf*(1-tf))^2,
    // tf = (x-lb0)/w - k. Int clamp of k keeps exactness: outside the
    // domain tf<0 or tf>1 -> p<0 -> fmax gives exact 0. Scale x16 at store.
    #pragma unroll
    for (int c = 0; c < CPG; c++) {
        {   // chain A (pos = lane)
            const float t  = fmaf(va[c], inv_w, c0);
            int k = __float2int_rd(t);
            k = max(0, min(k, CO - 1));
            const float tf = t - (float)k;
            const float p  = fmaf(tf, -tf, tf);   // tf*(1-tf)
            const float m  = fmaxf(p, 0.0f);
            float* a = aga + k * PPB;
            *a = fmaf(m, m, *a);
        }
        {   // chain B (pos = lane+32) — independent of chain A
            const float t  = fmaf(vb[c], inv_w, c0);
            int k = __float2int_rd(t);
            k = max(0, min(k, CO - 1));
            const float tf = t - (float)k;
            const float p  = fmaf(tf, -tf, tf);
            const float m  = fmaxf(p, 0.0f);
            float* a = agb + k * PPB;
            *a = fmaf(m, m, *a);
        }
    }
    __syncthreads();

    // Reduce the NG copies + store: 2048 outputs / 256 thr = 8 each.
    // Consecutive lanes -> consecutive o -> distinct banks, coalesced STG.
    #pragma unroll
    for (int i = 0; i < (CO * PPB) / NT; i++) {
        const int o  = tid + i * NT;        // 0..2047
        const int k  = o >> 6;              // o / PPB
        const int pp = o & (PPB - 1);       // o % PPB
        float sum = 0.0f;
        #pragma unroll
        for (int gg = 0; gg < NG; gg++)
            sum += acc[gg * (CO * PPB) + o];
        out[((size_t)b * CO + k) * HW + (s_base + pp)] = sum * 16.0f;
    }
}

extern "C" void kernel_launch(void* const* d_in, const int* in_sizes, int n_in,
                              void* d_out, int out_size)
{
    const float* x  = (const float*)d_in[0];
    const float* lb = (const float*)d_in[1];
    const float* rb = (const float*)d_in[2];
    float* out      = (float*)d_out;

    // 64 KB dynamic smem needs the opt-in attribute (host-side state change,
    // not an allocation; safe under graph capture). Idempotent per launch.
    cudaFuncSetAttribute(local_basis_kernel,
                         cudaFuncAttributeMaxDynamicSharedMemorySize,
                         ACCN * sizeof(float));

    local_basis_kernel<<<NPOS / PPB, NT, ACCN * sizeof(float)>>>(x, lb, rb, out);
}